// round 7
// baseline (speedup 1.0000x reference)
#include <cuda_runtime.h>
#include <cuda_bf16.h>
#include <cstdint>
#include <mma.h>

using namespace nvcuda;

// Problem constants
#define B_  8
#define T_  2048
#define D_  1024
#define H_  1024
#define R_  128
#define M_  (B_*T_)      // 16384 rows
#define C_  16           // scan chunks
#define L_  128          // chunk length (T_/C_)

// ---------------------------------------------------------------------------
// Scratch (device globals: allocation APIs are forbidden)
// ---------------------------------------------------------------------------
__device__ float d_tmp[(size_t)M_ * 2 * R_];            // [M,256]: x@U1 | x@U2
__device__ float d_e1[B_ * C_ * H_], d_e2[B_ * C_ * H_];
__device__ float d_i1[B_ * C_ * H_], d_i2[B_ * C_ * H_];
__device__ float d_g[H_], d_phi[H_], d_gamma[H_];

// ---------------------------------------------------------------------------
__global__ void param_kernel(const float* __restrict__ nu_log,
                             const float* __restrict__ theta_log) {
    int h = blockIdx.x * blockDim.x + threadIdx.x;
    if (h < H_) {
        float r = expf(-expf(nu_log[h]));
        float th = expf(theta_log[h]);
        d_g[h]   = r * cosf(th);
        d_phi[h] = r * sinf(th);
        float om = 1.0f - r * r;
        d_gamma[h] = sqrtf(fmaxf(om, 0.0f));
    }
}

// cp.async helpers
__device__ __forceinline__ void cp_async16(void* dst, const void* src) {
    unsigned s = (unsigned)__cvta_generic_to_shared(dst);
    asm volatile("cp.async.ca.shared.global [%0], [%1], 16;" :: "r"(s), "l"(src));
}
__device__ __forceinline__ void cp_commit() { asm volatile("cp.async.commit_group;"); }
template <int N>
__device__ __forceinline__ void cp_wait() { asm volatile("cp.async.wait_group %0;" :: "n"(N)); }

template <typename F>
__device__ __forceinline__ void cvt_frag(F& f) {
#pragma unroll
    for (int t = 0; t < f.num_elements; t++) f.x[t] = wmma::__float_to_tf32(f.x[t]);
}

// ---------------------------------------------------------------------------
// Stage 1: tmp[M,256] = x @ [U1 | U2]   (K = 1024)
// BM=128, BN=256 (x read exactly once), 512 threads = 16 warps (4x4),
// warp tile 32x64, KT=16, cp.async double buffer. Dynamic smem 53760 B.
// ---------------------------------------------------------------------------
__global__ __launch_bounds__(512, 1)
void gemm1(const float* __restrict__ x, const float* __restrict__ U1,
           const float* __restrict__ U2, float* __restrict__ tmp) {
    extern __shared__ float sm[];
    float* As = sm;            // [2][128][20]  = 5120 floats
    float* Bs = sm + 5120;     // [2][16][260]  = 8320 floats

    const int tid  = threadIdx.x;
    const int warp = tid >> 5;
    const int wm = warp >> 2;          // 0..3
    const int wn = warp & 3;           // 0..3
    const int m0 = blockIdx.x * 128;

    const int a_row = tid >> 2, a_col = (tid & 3) * 4;     // 128x16, 1 chunk
    const int b_row = tid >> 5, b_col = (tid & 31) * 8;    // 16x256, 2 chunks

    auto load_stage = [&](int s, int k0) {
        cp_async16(&As[(s * 128 + a_row) * 20 + a_col],
                   &x[(size_t)(m0 + a_row) * D_ + k0 + a_col]);
        const float* s0 = (b_col < R_)
            ? &U1[(size_t)(k0 + b_row) * R_ + b_col]
            : &U2[(size_t)(k0 + b_row) * R_ + b_col - R_];
        cp_async16(&Bs[(s * 16 + b_row) * 260 + b_col], s0);
        const float* s1 = (b_col + 4 < R_)
            ? &U1[(size_t)(k0 + b_row) * R_ + b_col + 4]
            : &U2[(size_t)(k0 + b_row) * R_ + b_col + 4 - R_];
        cp_async16(&Bs[(s * 16 + b_row) * 260 + b_col + 4], s1);
        cp_commit();
    };

    wmma::fragment<wmma::accumulator, 16, 16, 8, float> acc[2][4];
#pragma unroll
    for (int i = 0; i < 2; i++)
#pragma unroll
        for (int j = 0; j < 4; j++) wmma::fill_fragment(acc[i][j], 0.0f);

    load_stage(0, 0);
    const int nK = D_ / 16;
    for (int kt = 0; kt < nK; kt++) {
        const int s = kt & 1;
        if (kt + 1 < nK) { load_stage(1 - s, (kt + 1) * 16); cp_wait<1>(); }
        else             { cp_wait<0>(); }
        __syncthreads();

#pragma unroll
        for (int ks = 0; ks < 2; ks++) {
            wmma::fragment<wmma::matrix_a, 16, 16, 8, wmma::precision::tf32, wmma::row_major> af[2];
            wmma::fragment<wmma::matrix_b, 16, 16, 8, wmma::precision::tf32, wmma::row_major> bf[4];
#pragma unroll
            for (int i = 0; i < 2; i++) {
                wmma::load_matrix_sync(af[i], &As[(s * 128 + wm * 32 + i * 16) * 20 + ks * 8], 20);
                cvt_frag(af[i]);
            }
#pragma unroll
            for (int j = 0; j < 4; j++) {
                wmma::load_matrix_sync(bf[j], &Bs[(s * 16 + ks * 8) * 260 + wn * 64 + j * 16], 260);
                cvt_frag(bf[j]);
            }
#pragma unroll
            for (int i = 0; i < 2; i++)
#pragma unroll
                for (int j = 0; j < 4; j++)
                    wmma::mma_sync(acc[i][j], af[i], bf[j], acc[i][j]);
        }
        __syncthreads();
    }

    // Direct global stores (tmp write is only 16 MB)
#pragma unroll
    for (int i = 0; i < 2; i++)
#pragma unroll
        for (int j = 0; j < 4; j++)
            wmma::store_matrix_sync(
                &tmp[(size_t)(m0 + wm * 32 + i * 16) * 256 + wn * 64 + j * 16],
                acc[i][j], 256, wmma::mem_row_major);
}

// ---------------------------------------------------------------------------
// Fused stage-2 GEMM + chunk scan.
// Block = (h-tile 64, chunk j, batch b); 256 threads = 8 warps (4m x 2n).
// Computes bx = (tmp1 @ V1)*gamma, by = (tmp2 @ V2)*gamma for its 128t x 64h
// tile in registers (tmp is L2-resident), dumps to smem, scans 128 steps.
// FINAL=0: zero-init scan, emit chunk ends e1/e2.
// FINAL=1: init from i1/i2, write y tile coalesced + finals at last chunk.
// Dynamic smem 69632 B (staging 58368 B aliased with scan tiles).
// ---------------------------------------------------------------------------
template <int FINAL>
__global__ __launch_bounds__(256, 2)
void fused_scan(const float* __restrict__ tmp,
                const float* __restrict__ V1, const float* __restrict__ V2,
                const float* __restrict__ i1, const float* __restrict__ i2,
                float* __restrict__ e1, float* __restrict__ e2,
                float* __restrict__ out) {
    extern __shared__ float sm[];
    float* As1 = sm;             // [2][128][20] = 5120
    float* As2 = sm + 5120;      // [2][128][20] = 5120
    float* Bs1 = sm + 10240;     // [2][16][68]  = 2176
    float* Bs2 = sm + 12416;     // [2][16][68]  = 2176

    const int tid  = threadIdx.x;
    const int warp = tid >> 5;
    const int wm = warp >> 1;          // 0..3
    const int wn = warp & 1;           // 0..1
    const int h0 = blockIdx.x * 64;
    const int j  = blockIdx.y;
    const int b  = blockIdx.z;
    const int m0 = b * T_ + j * L_;    // tmp row base

    const int a_row = tid >> 1, a_col = (tid & 1) * 8;     // 128x16, 2 chunks each half
    const int b_row = tid >> 4, b_col = (tid & 15) * 4;    // 16x64, 1 chunk each

    auto load_stage = [&](int s, int k0) {
        const float* t1 = &tmp[(size_t)(m0 + a_row) * 256 + k0 + a_col];
        cp_async16(&As1[(s * 128 + a_row) * 20 + a_col],     t1);
        cp_async16(&As1[(s * 128 + a_row) * 20 + a_col + 4], t1 + 4);
        cp_async16(&As2[(s * 128 + a_row) * 20 + a_col],     t1 + R_);
        cp_async16(&As2[(s * 128 + a_row) * 20 + a_col + 4], t1 + R_ + 4);
        cp_async16(&Bs1[(s * 16 + b_row) * 68 + b_col],
                   &V1[(size_t)(k0 + b_row) * H_ + h0 + b_col]);
        cp_async16(&Bs2[(s * 16 + b_row) * 68 + b_col],
                   &V2[(size_t)(k0 + b_row) * H_ + h0 + b_col]);
        cp_commit();
    };

    wmma::fragment<wmma::accumulator, 16, 16, 8, float> accx[2][2], accy[2][2];
#pragma unroll
    for (int i = 0; i < 2; i++)
#pragma unroll
        for (int q = 0; q < 2; q++) {
            wmma::fill_fragment(accx[i][q], 0.0f);
            wmma::fill_fragment(accy[i][q], 0.0f);
        }

    load_stage(0, 0);
    const int nK = R_ / 16;   // 8
    for (int kt = 0; kt < nK; kt++) {
        const int s = kt & 1;
        if (kt + 1 < nK) { load_stage(1 - s, (kt + 1) * 16); cp_wait<1>(); }
        else             { cp_wait<0>(); }
        __syncthreads();

#pragma unroll
        for (int ks = 0; ks < 2; ks++) {
            wmma::fragment<wmma::matrix_a, 16, 16, 8, wmma::precision::tf32, wmma::row_major> af;
            wmma::fragment<wmma::matrix_b, 16, 16, 8, wmma::precision::tf32, wmma::row_major> bf;
#pragma unroll
            for (int i = 0; i < 2; i++) {
                wmma::load_matrix_sync(af, &As1[(s * 128 + wm * 32 + i * 16) * 20 + ks * 8], 20);
                cvt_frag(af);
#pragma unroll
                for (int q = 0; q < 2; q++) {
                    wmma::load_matrix_sync(bf, &Bs1[(s * 16 + ks * 8) * 68 + wn * 32 + q * 16], 68);
                    cvt_frag(bf);
                    wmma::mma_sync(accx[i][q], af, bf, accx[i][q]);
                }
                wmma::load_matrix_sync(af, &As2[(s * 128 + wm * 32 + i * 16) * 20 + ks * 8], 20);
                cvt_frag(af);
#pragma unroll
                for (int q = 0; q < 2; q++) {
                    wmma::load_matrix_sync(bf, &Bs2[(s * 16 + ks * 8) * 68 + wn * 32 + q * 16], 68);
                    cvt_frag(bf);
                    wmma::mma_sync(accy[i][q], af, bf, accy[i][q]);
                }
            }
        }
        __syncthreads();
    }

    // Dump accumulators to scan tiles (alias staging; all reads done)
    float* bxs = sm;           // [128][68]
    float* bys = sm + 8704;    // [128][68]
#pragma unroll
    for (int i = 0; i < 2; i++)
#pragma unroll
        for (int q = 0; q < 2; q++) {
            int tr = wm * 32 + i * 16, nc = wn * 32 + q * 16;
            wmma::store_matrix_sync(&bxs[tr * 68 + nc], accx[i][q], 68, wmma::mem_row_major);
            wmma::store_matrix_sync(&bys[tr * 68 + nc], accy[i][q], 68, wmma::mem_row_major);
        }
    __syncthreads();

    // Scan 128 steps (64 scan threads, one per channel in the tile)
    if (tid < 64) {
        int h = h0 + tid;
        float gg = d_g[h], pp = d_phi[h], gm = d_gamma[h];
        float c1, c2;
        if (FINAL) {
            c1 = i1[(b * C_ + j) * H_ + h];
            c2 = i2[(b * C_ + j) * H_ + h];
        } else {
            c1 = 0.f; c2 = 0.f;
        }
#pragma unroll 4
        for (int t = 0; t < L_; t++) {
            float bx = bxs[t * 68 + tid] * gm;
            float by = bys[t * 68 + tid] * gm;
            float n1 = fmaf(gg, c1, fmaf(-pp, c2, bx));
            float n2 = fmaf(pp, c1, fmaf(gg, c2, by));
            c1 = n1; c2 = n2;
            if (FINAL) { bxs[t * 68 + tid] = c1; bys[t * 68 + tid] = c2; }
        }
        if (!FINAL) {
            e1[(b * C_ + j) * H_ + h] = c1;
            e2[(b * C_ + j) * H_ + h] = c2;
        } else if (j == C_ - 1) {
            size_t y_elems = (size_t)B_ * T_ * (2 * H_);
            out[y_elems + b * H_ + h]            = c1;
            out[y_elems + B_ * H_ + b * H_ + h]  = c2;
        }
    }

    if (FINAL) {
        __syncthreads();
        // Coalesced y writes: 128 rows x 64 cols, c1 then c2 region
        int col = tid & 63;
        for (int t = tid >> 6; t < L_; t += 4) {
            size_t row = (size_t)(m0 + t) * (2 * H_);
            out[row + h0 + col]       = bxs[t * 68 + col];
            out[row + H_ + h0 + col]  = bys[t * 68 + col];
        }
    }
}

// ---------------------------------------------------------------------------
// Combine: propagate chunk inits (lambda^128 via 7 complex squarings)
// ---------------------------------------------------------------------------
__global__ void combine_kernel(const float* __restrict__ e1,
                               const float* __restrict__ e2,
                               const float* __restrict__ hc1,
                               const float* __restrict__ hc2,
                               float* __restrict__ i1, float* __restrict__ i2) {
    int idx = blockIdx.x * blockDim.x + threadIdx.x;    // B*H
    int h = idx & (H_ - 1);
    int b = idx >> 10;
    float lr = d_g[h], li = d_phi[h];
#pragma unroll
    for (int s = 0; s < 7; s++) {
        float nr = lr * lr - li * li;
        float ni = 2.0f * lr * li;
        lr = nr; li = ni;
    }
    float c1 = hc1[idx], c2 = hc2[idx];
#pragma unroll
    for (int j = 0; j < C_; j++) {
        int eidx = (b * C_ + j) * H_ + h;
        i1[eidx] = c1; i2[eidx] = c2;
        float n1 = lr * c1 - li * c2 + e1[eidx];
        float n2 = li * c1 + lr * c2 + e2[eidx];
        c1 = n1; c2 = n2;
    }
}

// ---------------------------------------------------------------------------
// Launch
// ---------------------------------------------------------------------------
extern "C" void kernel_launch(void* const* d_in, const int* in_sizes, int n_in,
                              void* d_out, int out_size) {
    const float* x         = (const float*)d_in[0];
    const float* nu_log    = (const float*)d_in[1];
    const float* theta_log = (const float*)d_in[2];
    const float* U1        = (const float*)d_in[3];
    const float* U2        = (const float*)d_in[4];
    const float* V1        = (const float*)d_in[5];
    const float* V2        = (const float*)d_in[6];
    const float* hc1       = (const float*)d_in[7];
    const float* hc2       = (const float*)d_in[8];
    float* out = (float*)d_out;

    float *tmp, *e1, *e2, *i1, *i2;
    cudaGetSymbolAddress((void**)&tmp, d_tmp);
    cudaGetSymbolAddress((void**)&e1, d_e1);
    cudaGetSymbolAddress((void**)&e2, d_e2);
    cudaGetSymbolAddress((void**)&i1, d_i1);
    cudaGetSymbolAddress((void**)&i2, d_i2);

    const int smem1 = (5120 + 8320) * 4;           // 53760 B
    const int smem2 = (8704 + 8704) * 4;           // 69632 B
    cudaFuncSetAttribute(gemm1, cudaFuncAttributeMaxDynamicSharedMemorySize, smem1);
    cudaFuncSetAttribute(fused_scan<0>, cudaFuncAttributeMaxDynamicSharedMemorySize, smem2);
    cudaFuncSetAttribute(fused_scan<1>, cudaFuncAttributeMaxDynamicSharedMemorySize, smem2);

    param_kernel<<<(H_ + 255) / 256, 256>>>(nu_log, theta_log);

    // Stage 1: tmp = x @ [U1|U2]   (x read once)
    gemm1<<<M_ / 128, 512, smem1>>>(x, U1, U2, tmp);

    // Phase A: fused GEMM + chunk-local scan -> chunk ends
    dim3 fgrid(H_ / 64, C_, B_);
    fused_scan<0><<<fgrid, 256, smem2>>>(tmp, V1, V2, nullptr, nullptr, e1, e2, out);

    // Combine chunk inits
    combine_kernel<<<(B_ * H_) / 256, 256>>>(e1, e2, hc1, hc2, i1, i2);

    // Phase B: fused GEMM + scan with inits -> y + finals
    fused_scan<1><<<fgrid, 256, smem2>>>(tmp, V1, V2, i1, i2, nullptr, nullptr, out);
}

// round 8
// speedup vs baseline: 1.2538x; 1.2538x over previous
#include <cuda_runtime.h>
#include <cuda_bf16.h>
#include <cstdint>
#include <mma.h>

using namespace nvcuda;

// Problem constants
#define B_  8
#define T_  2048
#define D_  1024
#define H_  1024
#define R_  128
#define M_  (B_*T_)      // 16384 rows
#define C_  16           // scan chunks
#define L_  128          // chunk length (T_/C_)

// ---------------------------------------------------------------------------
// Scratch (device globals: allocation APIs are forbidden)
// ---------------------------------------------------------------------------
__device__ float d_tmp[(size_t)M_ * 2 * R_];            // [M,256]: x@U1 | x@U2
__device__ float d_bxby[(size_t)M_ * 2 * H_];           // 128 MB
__device__ float d_e1[B_ * C_ * H_], d_e2[B_ * C_ * H_];
__device__ float d_i1[B_ * C_ * H_], d_i2[B_ * C_ * H_];
__device__ float d_g[H_], d_phi[H_], d_gamma[H_];

// ---------------------------------------------------------------------------
__global__ void param_kernel(const float* __restrict__ nu_log,
                             const float* __restrict__ theta_log) {
    int h = blockIdx.x * blockDim.x + threadIdx.x;
    if (h < H_) {
        float r = expf(-expf(nu_log[h]));
        float th = expf(theta_log[h]);
        d_g[h]   = r * cosf(th);
        d_phi[h] = r * sinf(th);
        float om = 1.0f - r * r;
        d_gamma[h] = sqrtf(fmaxf(om, 0.0f));
    }
}

// cp.async helpers
__device__ __forceinline__ void cp_async16(void* dst, const void* src) {
    unsigned s = (unsigned)__cvta_generic_to_shared(dst);
    asm volatile("cp.async.ca.shared.global [%0], [%1], 16;" :: "r"(s), "l"(src));
}
__device__ __forceinline__ void cp_commit() { asm volatile("cp.async.commit_group;"); }
template <int N>
__device__ __forceinline__ void cp_wait() { asm volatile("cp.async.wait_group %0;" :: "n"(N)); }

template <typename F>
__device__ __forceinline__ void cvt_frag(F& f) {
#pragma unroll
    for (int t = 0; t < f.num_elements; t++) f.x[t] = wmma::__float_to_tf32(f.x[t]);
}

// ---------------------------------------------------------------------------
// Unified tf32 GEMM: BM=128, BN=256, 512 threads (16 warps, 4x4; 32x64/warp),
// KT=16, cp.async double buffer.
//   C cols [0,nsplit) from B0, [nsplit,...) from B1 (per-16B-chunk select).
// DUALA=1: block n0 >= nsplit reads A cols shifted by +R_ (tmp2 half).
// EPI=1: multiply by gamma[n % H] (staged through smem for float4 stores).
// Dynamic smem: (5120 + 8448) * 4 = 54272 B.
// ---------------------------------------------------------------------------
template <int DUALA, int EPI>
__global__ __launch_bounds__(512, 1)
void tf32_gemm(const float* __restrict__ A, int lda,
               const float* __restrict__ B0, const float* __restrict__ B1,
               int ldb, int nsplit, int K,
               float* __restrict__ C, int ldc,
               const float* __restrict__ gamma) {
    constexpr int ALD = 20;    // 16 + 4
    constexpr int BLD = 264;   // 256 + 8

    extern __shared__ float sm[];
    float* As = sm;            // [2][128][20]  = 5120 floats
    float* Bs = sm + 5120;     // [2][16][264]  = 8448 floats

    const int tid  = threadIdx.x;
    const int warp = tid >> 5;
    const int lane = tid & 31;
    const int wm = warp >> 2;          // 0..3
    const int wn = warp & 3;           // 0..3
    const int m0 = blockIdx.y * 128;
    const int n0 = blockIdx.x * 256;

    const int aoff = (DUALA && n0 >= nsplit) ? R_ : 0;

    const int a_row = tid >> 2, a_col = (tid & 3) * 4;     // 128x16, 1 chunk
    const int b_row = tid >> 5, b_col = (tid & 31) * 8;    // 16x256, 2 chunks

    auto bsrc = [&](int k0, int col) -> const float* {
        int n = n0 + col;
        return (n < nsplit) ? &B0[(size_t)(k0 + b_row) * ldb + n]
                            : &B1[(size_t)(k0 + b_row) * ldb + n - nsplit];
    };

    auto load_stage = [&](int s, int k0) {
        cp_async16(&As[(s * 128 + a_row) * ALD + a_col],
                   &A[(size_t)(m0 + a_row) * lda + aoff + k0 + a_col]);
        cp_async16(&Bs[(s * 16 + b_row) * BLD + b_col],     bsrc(k0, b_col));
        cp_async16(&Bs[(s * 16 + b_row) * BLD + b_col + 4], bsrc(k0, b_col + 4));
        cp_commit();
    };

    wmma::fragment<wmma::accumulator, 16, 16, 8, float> acc[2][4];
#pragma unroll
    for (int i = 0; i < 2; i++)
#pragma unroll
        for (int j = 0; j < 4; j++) wmma::fill_fragment(acc[i][j], 0.0f);

    load_stage(0, 0);
    const int nK = K / 16;
    for (int kt = 0; kt < nK; kt++) {
        const int s = kt & 1;
        if (kt + 1 < nK) { load_stage(1 - s, (kt + 1) * 16); cp_wait<1>(); }
        else             { cp_wait<0>(); }
        __syncthreads();

#pragma unroll
        for (int ks = 0; ks < 2; ks++) {
            wmma::fragment<wmma::matrix_a, 16, 16, 8, wmma::precision::tf32, wmma::row_major> af[2];
            wmma::fragment<wmma::matrix_b, 16, 16, 8, wmma::precision::tf32, wmma::row_major> bf[4];
#pragma unroll
            for (int i = 0; i < 2; i++) {
                wmma::load_matrix_sync(af[i], &As[(s * 128 + wm * 32 + i * 16) * ALD + ks * 8], ALD);
                cvt_frag(af[i]);
            }
#pragma unroll
            for (int j = 0; j < 4; j++) {
                wmma::load_matrix_sync(bf[j], &Bs[(s * 16 + ks * 8) * BLD + wn * 64 + j * 16], BLD);
                cvt_frag(bf[j]);
            }
#pragma unroll
            for (int i = 0; i < 2; i++)
#pragma unroll
                for (int j = 0; j < 4; j++)
                    wmma::mma_sync(acc[i][j], af[i], bf[j], acc[i][j]);
        }
        __syncthreads();
    }

    if (EPI == 0) {
        // Direct global stores (tmp write is only 16 MB)
#pragma unroll
        for (int i = 0; i < 2; i++)
#pragma unroll
            for (int j = 0; j < 4; j++)
                wmma::store_matrix_sync(
                    &C[(size_t)(m0 + wm * 32 + i * 16) * ldc + n0 + wn * 64 + j * 16],
                    acc[i][j], ldc, wmma::mem_row_major);
    } else {
        // Staged epilogue: gamma scale + float4 stores
        float* wbuf = sm + warp * 256;     // 16 warps * 256 floats = 4096 <= 5120
        const int lr = lane >> 1;
        const int lc = (lane & 1) * 8;
#pragma unroll
        for (int i = 0; i < 2; i++) {
#pragma unroll
            for (int j = 0; j < 4; j++) {
                wmma::store_matrix_sync(wbuf, acc[i][j], 16, wmma::mem_row_major);
                __syncwarp();
                int m = m0 + wm * 32 + i * 16 + lr;
                int n = n0 + wn * 64 + j * 16 + lc;
                float v[8];
#pragma unroll
                for (int e = 0; e < 8; e++) v[e] = wbuf[lr * 16 + lc + e] * gamma[(n & (H_ - 1)) + e];
                *(float4*)&C[(size_t)m * ldc + n]     = make_float4(v[0], v[1], v[2], v[3]);
                *(float4*)&C[(size_t)m * ldc + n + 4] = make_float4(v[4], v[5], v[6], v[7]);
                __syncwarp();
            }
        }
    }
}

// ---------------------------------------------------------------------------
// Chunk-parallel scan (R6 layout: idx -> b, chunk j, h; h fastest)
// ---------------------------------------------------------------------------
__global__ void scanA_kernel(const float* __restrict__ bxby,
                             float* __restrict__ e1, float* __restrict__ e2) {
    int idx = blockIdx.x * blockDim.x + threadIdx.x;    // B*C*H
    int h = idx & (H_ - 1);
    int j = (idx >> 10) & (C_ - 1);
    int b = idx >> 14;
    float gg = d_g[h], pp = d_phi[h];
    float c1 = 0.f, c2 = 0.f;
    const float* base = bxby + ((size_t)(b * T_ + j * L_)) * (2 * H_) + h;
#pragma unroll 4
    for (int t = 0; t < L_; t++) {
        float bx = base[t * (2 * H_)];
        float by = base[t * (2 * H_) + H_];
        float n1 = fmaf(gg, c1, fmaf(-pp, c2, bx));
        float n2 = fmaf(pp, c1, fmaf(gg, c2, by));
        c1 = n1; c2 = n2;
    }
    e1[idx] = c1; e2[idx] = c2;
}

__global__ void combine_kernel(const float* __restrict__ e1,
                               const float* __restrict__ e2,
                               const float* __restrict__ hc1,
                               const float* __restrict__ hc2,
                               float* __restrict__ i1, float* __restrict__ i2) {
    int idx = blockIdx.x * blockDim.x + threadIdx.x;    // B*H
    int h = idx & (H_ - 1);
    int b = idx >> 10;
    float lr = d_g[h], li = d_phi[h];
#pragma unroll
    for (int s = 0; s < 7; s++) {          // lambda^128
        float nr = lr * lr - li * li;
        float ni = 2.0f * lr * li;
        lr = nr; li = ni;
    }
    float c1 = hc1[idx], c2 = hc2[idx];
#pragma unroll
    for (int j = 0; j < C_; j++) {
        int eidx = (b * C_ + j) * H_ + h;
        i1[eidx] = c1; i2[eidx] = c2;
        float n1 = lr * c1 - li * c2 + e1[eidx];
        float n2 = li * c1 + lr * c2 + e2[eidx];
        c1 = n1; c2 = n2;
    }
}

__global__ void scanB_kernel(const float* __restrict__ bxby,
                             const float* __restrict__ i1,
                             const float* __restrict__ i2,
                             float* __restrict__ out) {
    int idx = blockIdx.x * blockDim.x + threadIdx.x;    // B*C*H
    int h = idx & (H_ - 1);
    int j = (idx >> 10) & (C_ - 1);
    int b = idx >> 14;
    float gg = d_g[h], pp = d_phi[h];
    float c1 = i1[idx], c2 = i2[idx];
    const float* base  = bxby + ((size_t)(b * T_ + j * L_)) * (2 * H_) + h;
    float*       ybase = out  + ((size_t)(b * T_ + j * L_)) * (2 * H_) + h;
#pragma unroll 4
    for (int t = 0; t < L_; t++) {
        float bx = base[t * (2 * H_)];
        float by = base[t * (2 * H_) + H_];
        float n1 = fmaf(gg, c1, fmaf(-pp, c2, bx));
        float n2 = fmaf(pp, c1, fmaf(gg, c2, by));
        c1 = n1; c2 = n2;
        ybase[t * (2 * H_)]      = c1;
        ybase[t * (2 * H_) + H_] = c2;
    }
    if (j == C_ - 1) {
        size_t y_elems = (size_t)B_ * T_ * (2 * H_);
        out[y_elems + b * H_ + h]            = c1;
        out[y_elems + B_ * H_ + b * H_ + h]  = c2;
    }
}

// ---------------------------------------------------------------------------
// Launch
// ---------------------------------------------------------------------------
extern "C" void kernel_launch(void* const* d_in, const int* in_sizes, int n_in,
                              void* d_out, int out_size) {
    const float* x         = (const float*)d_in[0];
    const float* nu_log    = (const float*)d_in[1];
    const float* theta_log = (const float*)d_in[2];
    const float* U1        = (const float*)d_in[3];
    const float* U2        = (const float*)d_in[4];
    const float* V1        = (const float*)d_in[5];
    const float* V2        = (const float*)d_in[6];
    const float* hc1       = (const float*)d_in[7];
    const float* hc2       = (const float*)d_in[8];
    float* out = (float*)d_out;

    float *tmp, *bxby, *gamma, *e1, *e2, *i1, *i2;
    cudaGetSymbolAddress((void**)&tmp,  d_tmp);
    cudaGetSymbolAddress((void**)&bxby, d_bxby);
    cudaGetSymbolAddress((void**)&gamma, d_gamma);
    cudaGetSymbolAddress((void**)&e1, d_e1);
    cudaGetSymbolAddress((void**)&e2, d_e2);
    cudaGetSymbolAddress((void**)&i1, d_i1);
    cudaGetSymbolAddress((void**)&i2, d_i2);

    const int smem = (5120 + 8448) * 4;    // 54272 B
    cudaFuncSetAttribute(tf32_gemm<0, 0>, cudaFuncAttributeMaxDynamicSharedMemorySize, smem);
    cudaFuncSetAttribute(tf32_gemm<1, 1>, cudaFuncAttributeMaxDynamicSharedMemorySize, smem);

    param_kernel<<<(H_ + 255) / 256, 256>>>(nu_log, theta_log);

    // Stage 1: tmp[:,0:128]=x@U1, tmp[:,128:256]=x@U2  (K=1024, x read once)
    tf32_gemm<0, 0><<<dim3(1, M_ / 128), 512, smem>>>(
        x, D_, U1, U2, R_, R_, D_, tmp, 2 * R_, nullptr);

    // Stage 2: bxby[:,0:H]=(tmp1@V1)*g, bxby[:,H:2H]=(tmp2@V2)*g  (K=128)
    tf32_gemm<1, 1><<<dim3(2 * H_ / 256, M_ / 128), 512, smem>>>(
        tmp, 2 * R_, V1, V2, H_, H_, R_, bxby, 2 * H_, gamma);

    // Stage 3: chunk-parallel scan
    scanA_kernel<<<(B_ * C_ * H_) / 256, 256>>>(bxby, e1, e2);
    combine_kernel<<<(B_ * H_) / 256, 256>>>(e1, e2, hc1, hc2, i1, i2);
    scanB_kernel<<<(B_ * C_ * H_) / 256, 256>>>(bxby, i1, i2, out);
}

// round 10
// speedup vs baseline: 1.3240x; 1.0560x over previous
#include <cuda_runtime.h>
#include <cuda_bf16.h>
#include <cstdint>
#include <mma.h>

using namespace nvcuda;

// Problem constants
#define B_  8
#define T_  2048
#define D_  1024
#define H_  1024
#define R_  128
#define M_  (B_*T_)      // 16384 rows
#define C_  16           // scan chunks
#define L_  128          // chunk length (T_/C_)

// ---------------------------------------------------------------------------
// Scratch (device globals: allocation APIs are forbidden)
// ---------------------------------------------------------------------------
__device__ float d_tmp[(size_t)M_ * 2 * R_];            // [M,256]: x@U1 | x@U2
__device__ float d_bxby[(size_t)M_ * 2 * H_];           // 128 MB
__device__ float d_e1[B_ * C_ * H_], d_e2[B_ * C_ * H_];
__device__ float d_i1[B_ * C_ * H_], d_i2[B_ * C_ * H_];
__device__ float d_g[H_], d_phi[H_], d_gamma[H_];

// ---------------------------------------------------------------------------
__global__ void param_kernel(const float* __restrict__ nu_log,
                             const float* __restrict__ theta_log) {
    int h = blockIdx.x * blockDim.x + threadIdx.x;
    if (h < H_) {
        float r = expf(-expf(nu_log[h]));
        float th = expf(theta_log[h]);
        d_g[h]   = r * cosf(th);
        d_phi[h] = r * sinf(th);
        float om = 1.0f - r * r;
        d_gamma[h] = sqrtf(fmaxf(om, 0.0f));
    }
}

// cp.async helpers
__device__ __forceinline__ void cp_async16(void* dst, const void* src) {
    unsigned s = (unsigned)__cvta_generic_to_shared(dst);
    asm volatile("cp.async.ca.shared.global [%0], [%1], 16;" :: "r"(s), "l"(src));
}
__device__ __forceinline__ void cp_commit() { asm volatile("cp.async.commit_group;"); }
template <int N>
__device__ __forceinline__ void cp_wait() { asm volatile("cp.async.wait_group %0;" :: "n"(N)); }

template <typename F>
__device__ __forceinline__ void cvt_frag(F& f) {
#pragma unroll
    for (int t = 0; t < f.num_elements; t++) f.x[t] = wmma::__float_to_tf32(f.x[t]);
}

// ---------------------------------------------------------------------------
// tf32 wmma GEMM: BM=128, BN=128, 256 threads (8 warps, 4m x 2n; 32x64/warp),
// KT=16, 3-stage cp.async pipeline, 2 CTAs/SM.
// Block's 128 output cols lie wholly in B0 ([0,nsplit)) or B1.
// DUALA=1: block with n0 >= nsplit reads A cols shifted +R_ (tmp2 half).
// EPI=1: gamma[n & (H-1)] scale via smem-staged epilogue.
// Dynamic smem: (3*2560 + 3*2112) * 4 = 56064 B.
// ---------------------------------------------------------------------------
template <int DUALA, int EPI>
__global__ __launch_bounds__(256, 2)
void tf32_gemm(const float* __restrict__ A, int lda,
               const float* __restrict__ B0, const float* __restrict__ B1,
               int ldb, int nsplit, int K,
               float* __restrict__ C, int ldc,
               const float* __restrict__ gamma) {
    constexpr int ALD = 20;                 // 16 + 4 floats
    constexpr int BLD = 132;                // 128 + 4 floats
    constexpr int ASTG = 128 * ALD;         // 2560 floats / stage
    constexpr int BSTG = 16 * BLD;          // 2112 floats / stage

    extern __shared__ float sm[];
    float* As = sm;                 // [3][128][20]
    float* Bs = sm + 3 * ASTG;      // [3][16][132]

    const int tid  = threadIdx.x;
    const int warp = tid >> 5;
    const int lane = tid & 31;
    const int wm = warp >> 1;       // 0..3
    const int wn = warp & 1;        // 0..1
    const int m0 = blockIdx.y * 128;
    const int n0 = blockIdx.x * 128;

    const float* Bp = (n0 < nsplit) ? B0 : B1;
    const int bn0   = (n0 < nsplit) ? n0 : n0 - nsplit;
    const int aoff  = (DUALA && n0 >= nsplit) ? R_ : 0;

    // Loader mappings (16B chunks, 2 per thread for each matrix)
    // A: 128 rows x 4 chunks/row;  B: 16 rows x 32 chunks/row
    auto load_stage = [&](int s, int k0) {
#pragma unroll
        for (int i = 0; i < 2; i++) {
            int q = tid + i * 256;
            int ar = q >> 2, ac = (q & 3) * 4;
            cp_async16(&As[s * ASTG + ar * ALD + ac],
                       &A[(size_t)(m0 + ar) * lda + aoff + k0 + ac]);
        }
#pragma unroll
        for (int i = 0; i < 2; i++) {
            int q = tid + i * 256;
            int br = q >> 5, bc = (q & 31) * 4;
            cp_async16(&Bs[s * BSTG + br * BLD + bc],
                       &Bp[(size_t)(k0 + br) * ldb + bn0 + bc]);
        }
        cp_commit();
    };

    wmma::fragment<wmma::accumulator, 16, 16, 8, float> acc[2][4];
#pragma unroll
    for (int i = 0; i < 2; i++)
#pragma unroll
        for (int j = 0; j < 4; j++) wmma::fill_fragment(acc[i][j], 0.0f);

    const int nK = K / 16;
    load_stage(0, 0);
    if (nK > 1) load_stage(1, 16);

    for (int kt = 0; kt < nK; kt++) {
        const int s = kt % 3;
        if (kt + 2 < nK) { load_stage((kt + 2) % 3, (kt + 2) * 16); cp_wait<2>(); }
        else if (kt + 1 < nK) { cp_wait<1>(); }
        else { cp_wait<0>(); }
        __syncthreads();

#pragma unroll
        for (int ks = 0; ks < 2; ks++) {
            wmma::fragment<wmma::matrix_a, 16, 16, 8, wmma::precision::tf32, wmma::row_major> af[2];
            wmma::fragment<wmma::matrix_b, 16, 16, 8, wmma::precision::tf32, wmma::row_major> bf[4];
#pragma unroll
            for (int i = 0; i < 2; i++) {
                wmma::load_matrix_sync(af[i], &As[s * ASTG + (wm * 32 + i * 16) * ALD + ks * 8], ALD);
                cvt_frag(af[i]);
            }
#pragma unroll
            for (int j = 0; j < 4; j++) {
                wmma::load_matrix_sync(bf[j], &Bs[s * BSTG + ks * 8 * BLD + wn * 64 + j * 16], BLD);
                cvt_frag(bf[j]);
            }
#pragma unroll
            for (int i = 0; i < 2; i++)
#pragma unroll
                for (int j = 0; j < 4; j++)
                    wmma::mma_sync(acc[i][j], af[i], bf[j], acc[i][j]);
        }
        __syncthreads();
    }

    if (EPI == 0) {
        // Direct global stores (tmp write is only 16 MB)
#pragma unroll
        for (int i = 0; i < 2; i++)
#pragma unroll
            for (int j = 0; j < 4; j++)
                wmma::store_matrix_sync(
                    &C[(size_t)(m0 + wm * 32 + i * 16) * ldc + n0 + wn * 64 + j * 16],
                    acc[i][j], ldc, wmma::mem_row_major);
    } else {
        // Staged epilogue: gamma scale + float4 stores
        float* wbuf = sm + warp * 256;      // 8 warps * 256 floats = 2048 <= smem
        const int lr = lane >> 1;
        const int lc = (lane & 1) * 8;
#pragma unroll
        for (int i = 0; i < 2; i++) {
#pragma unroll
            for (int j = 0; j < 4; j++) {
                wmma::store_matrix_sync(wbuf, acc[i][j], 16, wmma::mem_row_major);
                __syncwarp();
                int m = m0 + wm * 32 + i * 16 + lr;
                int n = n0 + wn * 64 + j * 16 + lc;
                float v[8];
#pragma unroll
                for (int e = 0; e < 8; e++)
                    v[e] = wbuf[lr * 16 + lc + e] * gamma[(n & (H_ - 1)) + e];
                *(float4*)&C[(size_t)m * ldc + n]     = make_float4(v[0], v[1], v[2], v[3]);
                *(float4*)&C[(size_t)m * ldc + n + 4] = make_float4(v[4], v[5], v[6], v[7]);
                __syncwarp();
            }
        }
    }
}

// ---------------------------------------------------------------------------
// Chunk-parallel scan (unchanged)
// ---------------------------------------------------------------------------
__global__ void scanA_kernel(const float* __restrict__ bxby,
                             float* __restrict__ e1, float* __restrict__ e2) {
    int idx = blockIdx.x * blockDim.x + threadIdx.x;    // B*C*H
    int h = idx & (H_ - 1);
    int j = (idx >> 10) & (C_ - 1);
    int b = idx >> 14;
    float gg = d_g[h], pp = d_phi[h];
    float c1 = 0.f, c2 = 0.f;
    const float* base = bxby + ((size_t)(b * T_ + j * L_)) * (2 * H_) + h;
#pragma unroll 4
    for (int t = 0; t < L_; t++) {
        float bx = base[t * (2 * H_)];
        float by = base[t * (2 * H_) + H_];
        float n1 = fmaf(gg, c1, fmaf(-pp, c2, bx));
        float n2 = fmaf(pp, c1, fmaf(gg, c2, by));
        c1 = n1; c2 = n2;
    }
    e1[idx] = c1; e2[idx] = c2;
}

__global__ void combine_kernel(const float* __restrict__ e1,
                               const float* __restrict__ e2,
                               const float* __restrict__ hc1,
                               const float* __restrict__ hc2,
                               float* __restrict__ i1, float* __restrict__ i2) {
    int idx = blockIdx.x * blockDim.x + threadIdx.x;    // B*H
    int h = idx & (H_ - 1);
    int b = idx >> 10;
    float lr = d_g[h], li = d_phi[h];
#pragma unroll
    for (int s = 0; s < 7; s++) {          // lambda^128
        float nr = lr * lr - li * li;
        float ni = 2.0f * lr * li;
        lr = nr; li = ni;
    }
    float c1 = hc1[idx], c2 = hc2[idx];
#pragma unroll
    for (int j = 0; j < C_; j++) {
        int eidx = (b * C_ + j) * H_ + h;
        i1[eidx] = c1; i2[eidx] = c2;
        float n1 = lr * c1 - li * c2 + e1[eidx];
        float n2 = li * c1 + lr * c2 + e2[eidx];
        c1 = n1; c2 = n2;
    }
}

__global__ void scanB_kernel(const float* __restrict__ bxby,
                             const float* __restrict__ i1,
                             const float* __restrict__ i2,
                             float* __restrict__ out) {
    int idx = blockIdx.x * blockDim.x + threadIdx.x;    // B*C*H
    int h = idx & (H_ - 1);
    int j = (idx >> 10) & (C_ - 1);
    int b = idx >> 14;
    float gg = d_g[h], pp = d_phi[h];
    float c1 = i1[idx], c2 = i2[idx];
    const float* base  = bxby + ((size_t)(b * T_ + j * L_)) * (2 * H_) + h;
    float*       ybase = out  + ((size_t)(b * T_ + j * L_)) * (2 * H_) + h;
#pragma unroll 4
    for (int t = 0; t < L_; t++) {
        float bx = base[t * (2 * H_)];
        float by = base[t * (2 * H_) + H_];
        float n1 = fmaf(gg, c1, fmaf(-pp, c2, bx));
        float n2 = fmaf(pp, c1, fmaf(gg, c2, by));
        c1 = n1; c2 = n2;
        ybase[t * (2 * H_)]      = c1;
        ybase[t * (2 * H_) + H_] = c2;
    }
    if (j == C_ - 1) {
        size_t y_elems = (size_t)B_ * T_ * (2 * H_);
        out[y_elems + b * H_ + h]            = c1;
        out[y_elems + B_ * H_ + b * H_ + h]  = c2;
    }
}

// ---------------------------------------------------------------------------
// Launch
// ---------------------------------------------------------------------------
extern "C" void kernel_launch(void* const* d_in, const int* in_sizes, int n_in,
                              void* d_out, int out_size) {
    const float* x         = (const float*)d_in[0];
    const float* nu_log    = (const float*)d_in[1];
    const float* theta_log = (const float*)d_in[2];
    const float* U1        = (const float*)d_in[3];
    const float* U2        = (const float*)d_in[4];
    const float* V1        = (const float*)d_in[5];
    const float* V2        = (const float*)d_in[6];
    const float* hc1       = (const float*)d_in[7];
    const float* hc2       = (const float*)d_in[8];
    float* out = (float*)d_out;

    float *tmp, *bxby, *gamma, *e1, *e2, *i1, *i2;
    cudaGetSymbolAddress((void**)&tmp,  d_tmp);
    cudaGetSymbolAddress((void**)&bxby, d_bxby);
    cudaGetSymbolAddress((void**)&gamma, d_gamma);
    cudaGetSymbolAddress((void**)&e1, d_e1);
    cudaGetSymbolAddress((void**)&e2, d_e2);
    cudaGetSymbolAddress((void**)&i1, d_i1);
    cudaGetSymbolAddress((void**)&i2, d_i2);

    const int smem = (3 * 2560 + 3 * 2112) * 4;    // 56064 B
    cudaFuncSetAttribute(tf32_gemm<0, 0>, cudaFuncAttributeMaxDynamicSharedMemorySize, smem);
    cudaFuncSetAttribute(tf32_gemm<1, 1>, cudaFuncAttributeMaxDynamicSharedMemorySize, smem);

    param_kernel<<<(H_ + 255) / 256, 256>>>(nu_log, theta_log);

    // Stage 1: tmp[:,0:128]=x@U1, tmp[:,128:256]=x@U2  (K=1024)
    tf32_gemm<0, 0><<<dim3(2, M_ / 128), 256, smem>>>(
        x, D_, U1, U2, R_, R_, D_, tmp, 2 * R_, nullptr);

    // Stage 2: bxby[:,0:H]=(tmp1@V1)*g, bxby[:,H:2H]=(tmp2@V2)*g  (K=128)
    tf32_gemm<1, 1><<<dim3(2 * H_ / 128, M_ / 128), 256, smem>>>(
        tmp, 2 * R_, V1, V2, H_, H_, R_, bxby, 2 * H_, gamma);

    // Stage 3: chunk-parallel scan
    scanA_kernel<<<(B_ * C_ * H_) / 256, 256>>>(bxby, e1, e2);
    combine_kernel<<<(B_ * H_) / 256, 256>>>(e1, e2, hc1, hc2, i1, i2);
    scanB_kernel<<<(B_ * C_ * H_) / 256, 256>>>(bxby, i1, i2, out);
}

// round 12
// speedup vs baseline: 2.6597x; 2.0088x over previous
#include <cuda_runtime.h>
#include <cuda_fp16.h>
#include <cstdint>
#include <mma.h>

using namespace nvcuda;

// Problem constants
#define B_  8
#define T_  2048
#define D_  1024
#define H_  1024
#define R_  128
#define M_  (B_*T_)      // 16384 rows
#define C_  16           // scan chunks
#define L_  128          // chunk length (T_/C_)

// ---------------------------------------------------------------------------
// Scratch (device globals: allocation APIs are forbidden)
// ---------------------------------------------------------------------------
__device__ __half d_xh[(size_t)M_ * D_];        // 32 MB
__device__ __half d_u1h[D_ * R_], d_u2h[D_ * R_];
__device__ __half d_v1h[R_ * H_], d_v2h[R_ * H_];   // pre-scaled by gamma
__device__ __half d_tmph[(size_t)M_ * 2 * R_];  // 8 MB: x@U1 | x@U2 (fp16)
__device__ float d_bxby[(size_t)M_ * 2 * H_];   // 128 MB
__device__ float d_e1[B_ * C_ * H_], d_e2[B_ * C_ * H_];
__device__ float d_i1[B_ * C_ * H_], d_i2[B_ * C_ * H_];
__device__ float d_g[H_], d_phi[H_], d_gamma[H_];

// ---------------------------------------------------------------------------
__global__ void param_kernel(const float* __restrict__ nu_log,
                             const float* __restrict__ theta_log) {
    int h = blockIdx.x * blockDim.x + threadIdx.x;
    if (h < H_) {
        float r = expf(-expf(nu_log[h]));
        float th = expf(theta_log[h]);
        d_g[h]   = r * cosf(th);
        d_phi[h] = r * sinf(th);
        float om = 1.0f - r * r;
        d_gamma[h] = sqrtf(fmaxf(om, 0.0f));
    }
}

// fp32 -> fp16, 8 elements/thread
__global__ void conv_x_kernel(const float* __restrict__ src,
                              __half* __restrict__ dst, int n8) {
    int i = blockIdx.x * blockDim.x + threadIdx.x;
    if (i >= n8) return;
    float4 a = ((const float4*)src)[i * 2];
    float4 b = ((const float4*)src)[i * 2 + 1];
    __half2 h[4];
    h[0] = __floats2half2_rn(a.x, a.y);
    h[1] = __floats2half2_rn(a.z, a.w);
    h[2] = __floats2half2_rn(b.x, b.y);
    h[3] = __floats2half2_rn(b.z, b.w);
    ((uint4*)dst)[i] = *(uint4*)h;
}

// U -> fp16 (no scale)
__global__ void conv_u_kernel(const float* __restrict__ U1,
                              const float* __restrict__ U2) {
    int i = blockIdx.x * blockDim.x + threadIdx.x;
    if (i >= D_ * R_) return;
    d_u1h[i] = __float2half_rn(U1[i]);
    d_u2h[i] = __float2half_rn(U2[i]);
}

// V -> fp16, columns pre-scaled by gamma[h]  (folds the gamma epilogue)
__global__ void conv_v_kernel(const float* __restrict__ V1,
                              const float* __restrict__ V2) {
    int i = blockIdx.x * blockDim.x + threadIdx.x;
    if (i >= R_ * H_) return;
    int h = i % H_;
    float gm = d_gamma[h];
    d_v1h[i] = __float2half_rn(V1[i] * gm);
    d_v2h[i] = __float2half_rn(V2[i] * gm);
}

// cp.async helpers
__device__ __forceinline__ void cp_async16(void* dst, const void* src) {
    unsigned s = (unsigned)__cvta_generic_to_shared(dst);
    asm volatile("cp.async.ca.shared.global [%0], [%1], 16;" :: "r"(s), "l"(src));
}
__device__ __forceinline__ void cp_commit() { asm volatile("cp.async.commit_group;"); }
template <int N>
__device__ __forceinline__ void cp_wait() { asm volatile("cp.async.wait_group %0;" :: "n"(N)); }

// ---------------------------------------------------------------------------
// fp16 wmma GEMM: BM=128, BN=128, KT=32; 256 threads (8 warps 4m x 2n, 32x64
// per warp); 3-stage cp.async pipeline; 2 CTAs/SM.
// Block's 128 cols lie wholly in B0 ([0,nsplit)) or B1 (per-block select).
// DUALA=1: block with n0 >= nsplit reads A cols shifted +R_ (tmp2 half).
// HOUT=1: write C as fp16 (staged); HOUT=0: direct fp32 store_matrix_sync.
// Dynamic smem: 3*(10240 + 8704) = 56832 B.
// ---------------------------------------------------------------------------
template <int DUALA, int HOUT>
__global__ __launch_bounds__(256, 2)
void h16_gemm(const __half* __restrict__ A, int lda,
              const __half* __restrict__ B0, const __half* __restrict__ B1,
              int ldb, int nsplit, int K,
              float* __restrict__ Cf, __half* __restrict__ Ch, int ldc) {
    constexpr int ALD = 40;                 // 32 + 8 halves (80 B rows)
    constexpr int BLD = 136;                // 128 + 8 halves (272 B rows)
    constexpr int ASTG = 128 * ALD;         // halves per stage
    constexpr int BSTG = 32 * BLD;

    extern __shared__ __align__(16) __half smh[];
    __half* As = smh;                  // [3][128][40]
    __half* Bs = smh + 3 * ASTG;       // [3][32][136]

    const int tid  = threadIdx.x;
    const int warp = tid >> 5;
    const int lane = tid & 31;
    const int wm = warp >> 1;          // 0..3
    const int wn = warp & 1;           // 0..1
    const int m0 = blockIdx.y * 128;
    const int n0 = blockIdx.x * 128;

    const __half* Bp = (n0 < nsplit) ? B0 : B1;
    const int bn0    = (n0 < nsplit) ? n0 : n0 - nsplit;
    const int aoff   = (DUALA && n0 >= nsplit) ? R_ : 0;

    // Loaders: A 128 rows x 4 16B-chunks (8 halves); B 32 rows x 16 chunks
    auto load_stage = [&](int s, int k0) {
#pragma unroll
        for (int i = 0; i < 2; i++) {
            int q = tid + i * 256;
            int ar = q >> 2, ac = (q & 3) * 8;
            cp_async16(&As[s * ASTG + ar * ALD + ac],
                       &A[(size_t)(m0 + ar) * lda + aoff + k0 + ac]);
        }
#pragma unroll
        for (int i = 0; i < 2; i++) {
            int q = tid + i * 256;
            int br = q >> 4, bc = (q & 15) * 8;
            cp_async16(&Bs[s * BSTG + br * BLD + bc],
                       &Bp[(size_t)(k0 + br) * ldb + bn0 + bc]);
        }
        cp_commit();
    };

    wmma::fragment<wmma::accumulator, 16, 16, 16, float> acc[2][4];
#pragma unroll
    for (int i = 0; i < 2; i++)
#pragma unroll
        for (int j = 0; j < 4; j++) wmma::fill_fragment(acc[i][j], 0.0f);

    const int nK = K / 32;
    load_stage(0, 0);
    if (nK > 1) load_stage(1, 32);

    for (int kt = 0; kt < nK; kt++) {
        const int s = kt % 3;
        if (kt + 2 < nK) { load_stage((kt + 2) % 3, (kt + 2) * 32); cp_wait<2>(); }
        else if (kt + 1 < nK) { cp_wait<1>(); }
        else { cp_wait<0>(); }
        __syncthreads();

#pragma unroll
        for (int ks = 0; ks < 2; ks++) {
            wmma::fragment<wmma::matrix_a, 16, 16, 16, __half, wmma::row_major> af[2];
            wmma::fragment<wmma::matrix_b, 16, 16, 16, __half, wmma::row_major> bf[4];
#pragma unroll
            for (int i = 0; i < 2; i++)
                wmma::load_matrix_sync(af[i], &As[s * ASTG + (wm * 32 + i * 16) * ALD + ks * 16], ALD);
#pragma unroll
            for (int j = 0; j < 4; j++)
                wmma::load_matrix_sync(bf[j], &Bs[s * BSTG + (ks * 16) * BLD + wn * 64 + j * 16], BLD);
#pragma unroll
            for (int i = 0; i < 2; i++)
#pragma unroll
                for (int j = 0; j < 4; j++)
                    wmma::mma_sync(acc[i][j], af[i], bf[j], acc[i][j]);
        }
        __syncthreads();
    }

    if (HOUT == 0) {
        // Direct fp32 stores (gamma already folded into B)
#pragma unroll
        for (int i = 0; i < 2; i++)
#pragma unroll
            for (int j = 0; j < 4; j++)
                wmma::store_matrix_sync(
                    &Cf[(size_t)(m0 + wm * 32 + i * 16) * ldc + n0 + wn * 64 + j * 16],
                    acc[i][j], ldc, wmma::mem_row_major);
    } else {
        // Staged epilogue: fp32 acc -> fp16, coalesced 16B stores
        float* wbuf = (float*)smh + warp * 256;
        const int lr = lane >> 1;
        const int lc = (lane & 1) * 8;
#pragma unroll
        for (int i = 0; i < 2; i++) {
#pragma unroll
            for (int j = 0; j < 4; j++) {
                wmma::store_matrix_sync(wbuf, acc[i][j], 16, wmma::mem_row_major);
                __syncwarp();
                int m = m0 + wm * 32 + i * 16 + lr;
                int n = n0 + wn * 64 + j * 16 + lc;
                __half2 h[4];
#pragma unroll
                for (int e = 0; e < 4; e++)
                    h[e] = __floats2half2_rn(wbuf[lr * 16 + lc + e * 2],
                                             wbuf[lr * 16 + lc + e * 2 + 1]);
                *(uint4*)&Ch[(size_t)m * ldc + n] = *(uint4*)h;   // FIX: 16B, was uint2 (8B)
                __syncwarp();
            }
        }
    }
}

// ---------------------------------------------------------------------------
// Chunk-parallel scan (unchanged)
// ---------------------------------------------------------------------------
__global__ void scanA_kernel(const float* __restrict__ bxby,
                             float* __restrict__ e1, float* __restrict__ e2) {
    int idx = blockIdx.x * blockDim.x + threadIdx.x;    // B*C*H
    int h = idx & (H_ - 1);
    int j = (idx >> 10) & (C_ - 1);
    int b = idx >> 14;
    float gg = d_g[h], pp = d_phi[h];
    float c1 = 0.f, c2 = 0.f;
    const float* base = bxby + ((size_t)(b * T_ + j * L_)) * (2 * H_) + h;
#pragma unroll 4
    for (int t = 0; t < L_; t++) {
        float bx = base[t * (2 * H_)];
        float by = base[t * (2 * H_) + H_];
        float n1 = fmaf(gg, c1, fmaf(-pp, c2, bx));
        float n2 = fmaf(pp, c1, fmaf(gg, c2, by));
        c1 = n1; c2 = n2;
    }
    e1[idx] = c1; e2[idx] = c2;
}

__global__ void combine_kernel(const float* __restrict__ e1,
                               const float* __restrict__ e2,
                               const float* __restrict__ hc1,
                               const float* __restrict__ hc2,
                               float* __restrict__ i1, float* __restrict__ i2) {
    int idx = blockIdx.x * blockDim.x + threadIdx.x;    // B*H
    int h = idx & (H_ - 1);
    int b = idx >> 10;
    float lr = d_g[h], li = d_phi[h];
#pragma unroll
    for (int s = 0; s < 7; s++) {          // lambda^128
        float nr = lr * lr - li * li;
        float ni = 2.0f * lr * li;
        lr = nr; li = ni;
    }
    float c1 = hc1[idx], c2 = hc2[idx];
#pragma unroll
    for (int j = 0; j < C_; j++) {
        int eidx = (b * C_ + j) * H_ + h;
        i1[eidx] = c1; i2[eidx] = c2;
        float n1 = lr * c1 - li * c2 + e1[eidx];
        float n2 = li * c1 + lr * c2 + e2[eidx];
        c1 = n1; c2 = n2;
    }
}

__global__ void scanB_kernel(const float* __restrict__ bxby,
                             const float* __restrict__ i1,
                             const float* __restrict__ i2,
                             float* __restrict__ out) {
    int idx = blockIdx.x * blockDim.x + threadIdx.x;    // B*C*H
    int h = idx & (H_ - 1);
    int j = (idx >> 10) & (C_ - 1);
    int b = idx >> 14;
    float gg = d_g[h], pp = d_phi[h];
    float c1 = i1[idx], c2 = i2[idx];
    const float* base  = bxby + ((size_t)(b * T_ + j * L_)) * (2 * H_) + h;
    float*       ybase = out  + ((size_t)(b * T_ + j * L_)) * (2 * H_) + h;
#pragma unroll 4
    for (int t = 0; t < L_; t++) {
        float bx = base[t * (2 * H_)];
        float by = base[t * (2 * H_) + H_];
        float n1 = fmaf(gg, c1, fmaf(-pp, c2, bx));
        float n2 = fmaf(pp, c1, fmaf(gg, c2, by));
        c1 = n1; c2 = n2;
        ybase[t * (2 * H_)]      = c1;
        ybase[t * (2 * H_) + H_] = c2;
    }
    if (j == C_ - 1) {
        size_t y_elems = (size_t)B_ * T_ * (2 * H_);
        out[y_elems + b * H_ + h]            = c1;
        out[y_elems + B_ * H_ + b * H_ + h]  = c2;
    }
}

// ---------------------------------------------------------------------------
// Launch
// ---------------------------------------------------------------------------
extern "C" void kernel_launch(void* const* d_in, const int* in_sizes, int n_in,
                              void* d_out, int out_size) {
    const float* x         = (const float*)d_in[0];
    const float* nu_log    = (const float*)d_in[1];
    const float* theta_log = (const float*)d_in[2];
    const float* U1        = (const float*)d_in[3];
    const float* U2        = (const float*)d_in[4];
    const float* V1        = (const float*)d_in[5];
    const float* V2        = (const float*)d_in[6];
    const float* hc1       = (const float*)d_in[7];
    const float* hc2       = (const float*)d_in[8];
    float* out = (float*)d_out;

    __half *xh, *u1h, *u2h, *v1h, *v2h, *tmph;
    float *bxby, *e1, *e2, *i1, *i2;
    cudaGetSymbolAddress((void**)&xh,   d_xh);
    cudaGetSymbolAddress((void**)&u1h,  d_u1h);
    cudaGetSymbolAddress((void**)&u2h,  d_u2h);
    cudaGetSymbolAddress((void**)&v1h,  d_v1h);
    cudaGetSymbolAddress((void**)&v2h,  d_v2h);
    cudaGetSymbolAddress((void**)&tmph, d_tmph);
    cudaGetSymbolAddress((void**)&bxby, d_bxby);
    cudaGetSymbolAddress((void**)&e1, d_e1);
    cudaGetSymbolAddress((void**)&e2, d_e2);
    cudaGetSymbolAddress((void**)&i1, d_i1);
    cudaGetSymbolAddress((void**)&i2, d_i2);

    const int smem = 3 * (128 * 40 + 32 * 136) * 2;    // 56832 B
    cudaFuncSetAttribute(h16_gemm<0, 1>, cudaFuncAttributeMaxDynamicSharedMemorySize, smem);
    cudaFuncSetAttribute(h16_gemm<1, 0>, cudaFuncAttributeMaxDynamicSharedMemorySize, smem);

    param_kernel<<<(H_ + 255) / 256, 256>>>(nu_log, theta_log);

    // Conversions (gamma folded into V)
    int n8 = (M_ * D_) / 8;
    conv_x_kernel<<<(n8 + 255) / 256, 256>>>(x, xh, n8);
    conv_u_kernel<<<(D_ * R_ + 255) / 256, 256>>>(U1, U2);
    conv_v_kernel<<<(R_ * H_ + 255) / 256, 256>>>(V1, V2);

    // Stage 1: tmph[:,0:128]=x@U1, tmph[:,128:256]=x@U2  (K=1024, fp16 out)
    h16_gemm<0, 1><<<dim3(2, M_ / 128), 256, smem>>>(
        xh, D_, u1h, u2h, R_, R_, D_, nullptr, tmph, 2 * R_);

    // Stage 2: bxby[:,0:H]=tmp1@(V1*g), bxby[:,H:2H]=tmp2@(V2*g)  (K=128, fp32 out)
    h16_gemm<1, 0><<<dim3(2 * H_ / 128, M_ / 128), 256, smem>>>(
        tmph, 2 * R_, v1h, v2h, H_, H_, R_, bxby, nullptr, 2 * H_);

    // Stage 3: chunk-parallel scan
    scanA_kernel<<<(B_ * C_ * H_) / 256, 256>>>(bxby, e1, e2);
    combine_kernel<<<(B_ * H_) / 256, 256>>>(e1, e2, hc1, hc2, i1, i2);
    scanB_kernel<<<(B_ * C_ * H_) / 256, 256>>>(bxby, i1, i2, out);
}

// round 13
// speedup vs baseline: 2.8483x; 1.0709x over previous
#include <cuda_runtime.h>
#include <cuda_fp16.h>
#include <cstdint>
#include <mma.h>

using namespace nvcuda;

// Problem constants
#define B_  8
#define T_  2048
#define D_  1024
#define H_  1024
#define R_  128
#define M_  (B_*T_)      // 16384 rows
#define C_  16           // scan chunks
#define L_  128          // chunk length (T_/C_)

// ---------------------------------------------------------------------------
// Scratch (device globals: allocation APIs are forbidden)
// ---------------------------------------------------------------------------
__device__ __half d_xh[(size_t)M_ * D_];        // 32 MB
__device__ __half d_u1h[D_ * R_], d_u2h[D_ * R_];
__device__ __half d_v1h[R_ * H_], d_v2h[R_ * H_];   // pre-scaled by gamma
__device__ __half d_tmph[(size_t)M_ * 2 * R_];  // 8 MB: x@U1 | x@U2 (fp16)
__device__ __half d_bxbyh[(size_t)M_ * 2 * H_]; // 64 MB (fp16)
__device__ float d_e1[B_ * C_ * H_], d_e2[B_ * C_ * H_];
__device__ float d_i1[B_ * C_ * H_], d_i2[B_ * C_ * H_];
__device__ float d_g[H_], d_phi[H_];

// ---------------------------------------------------------------------------
// Prep: decay params + U conv + V conv (gamma recomputed per V-thread, so no
// cross-thread dependency). Grid covers R_*H_ threads.
// ---------------------------------------------------------------------------
__global__ void prep_kernel(const float* __restrict__ nu_log,
                            const float* __restrict__ theta_log,
                            const float* __restrict__ U1,
                            const float* __restrict__ U2,
                            const float* __restrict__ V1,
                            const float* __restrict__ V2) {
    int i = blockIdx.x * blockDim.x + threadIdx.x;
    if (i < H_) {
        float r = expf(-expf(nu_log[i]));
        float th = expf(theta_log[i]);
        d_g[i]   = r * cosf(th);
        d_phi[i] = r * sinf(th);
    }
    if (i < D_ * R_) {
        d_u1h[i] = __float2half_rn(U1[i]);
        d_u2h[i] = __float2half_rn(U2[i]);
    }
    if (i < R_ * H_) {
        int h = i % H_;
        float r = expf(-expf(nu_log[h]));
        float gm = sqrtf(fmaxf(1.0f - r * r, 0.0f));
        d_v1h[i] = __float2half_rn(V1[i] * gm);
        d_v2h[i] = __float2half_rn(V2[i] * gm);
    }
}

// fp32 -> fp16, 8 elements/thread
__global__ void conv_x_kernel(const float* __restrict__ src,
                              __half* __restrict__ dst, int n8) {
    int i = blockIdx.x * blockDim.x + threadIdx.x;
    if (i >= n8) return;
    float4 a = ((const float4*)src)[i * 2];
    float4 b = ((const float4*)src)[i * 2 + 1];
    __half2 h[4];
    h[0] = __floats2half2_rn(a.x, a.y);
    h[1] = __floats2half2_rn(a.z, a.w);
    h[2] = __floats2half2_rn(b.x, b.y);
    h[3] = __floats2half2_rn(b.z, b.w);
    ((uint4*)dst)[i] = *(uint4*)h;
}

// cp.async helpers
__device__ __forceinline__ void cp_async16(void* dst, const void* src) {
    unsigned s = (unsigned)__cvta_generic_to_shared(dst);
    asm volatile("cp.async.ca.shared.global [%0], [%1], 16;" :: "r"(s), "l"(src));
}
__device__ __forceinline__ void cp_commit() { asm volatile("cp.async.commit_group;"); }
template <int N>
__device__ __forceinline__ void cp_wait() { asm volatile("cp.async.wait_group %0;" :: "n"(N)); }

// ---------------------------------------------------------------------------
// fp16 wmma GEMM: BM=128, BN=128, KT=32; 256 threads (8 warps 4m x 2n, 32x64
// per warp); 3-stage cp.async pipeline; 2 CTAs/SM. fp16 output (staged).
// DUALA=1: block with n0 >= nsplit reads A cols shifted +R_ (tmp2 half).
// Dynamic smem: 3*(10240 + 8704) = 56832 B.
// ---------------------------------------------------------------------------
template <int DUALA>
__global__ __launch_bounds__(256, 2)
void h16_gemm(const __half* __restrict__ A, int lda,
              const __half* __restrict__ B0, const __half* __restrict__ B1,
              int ldb, int nsplit, int K,
              __half* __restrict__ Ch, int ldc) {
    constexpr int ALD = 40;                 // 32 + 8 halves (80 B rows)
    constexpr int BLD = 136;                // 128 + 8 halves (272 B rows)
    constexpr int ASTG = 128 * ALD;
    constexpr int BSTG = 32 * BLD;

    extern __shared__ __align__(16) __half smh[];
    __half* As = smh;                  // [3][128][40]
    __half* Bs = smh + 3 * ASTG;       // [3][32][136]

    const int tid  = threadIdx.x;
    const int warp = tid >> 5;
    const int lane = tid & 31;
    const int wm = warp >> 1;          // 0..3
    const int wn = warp & 1;           // 0..1
    const int m0 = blockIdx.y * 128;
    const int n0 = blockIdx.x * 128;

    const __half* Bp = (n0 < nsplit) ? B0 : B1;
    const int bn0    = (n0 < nsplit) ? n0 : n0 - nsplit;
    const int aoff   = (DUALA && n0 >= nsplit) ? R_ : 0;

    auto load_stage = [&](int s, int k0) {
#pragma unroll
        for (int i = 0; i < 2; i++) {
            int q = tid + i * 256;
            int ar = q >> 2, ac = (q & 3) * 8;
            cp_async16(&As[s * ASTG + ar * ALD + ac],
                       &A[(size_t)(m0 + ar) * lda + aoff + k0 + ac]);
        }
#pragma unroll
        for (int i = 0; i < 2; i++) {
            int q = tid + i * 256;
            int br = q >> 4, bc = (q & 15) * 8;
            cp_async16(&Bs[s * BSTG + br * BLD + bc],
                       &Bp[(size_t)(k0 + br) * ldb + bn0 + bc]);
        }
        cp_commit();
    };

    wmma::fragment<wmma::accumulator, 16, 16, 16, float> acc[2][4];
#pragma unroll
    for (int i = 0; i < 2; i++)
#pragma unroll
        for (int j = 0; j < 4; j++) wmma::fill_fragment(acc[i][j], 0.0f);

    const int nK = K / 32;
    load_stage(0, 0);
    if (nK > 1) load_stage(1, 32);

    for (int kt = 0; kt < nK; kt++) {
        const int s = kt % 3;
        if (kt + 2 < nK) { load_stage((kt + 2) % 3, (kt + 2) * 32); cp_wait<2>(); }
        else if (kt + 1 < nK) { cp_wait<1>(); }
        else { cp_wait<0>(); }
        __syncthreads();

#pragma unroll
        for (int ks = 0; ks < 2; ks++) {
            wmma::fragment<wmma::matrix_a, 16, 16, 16, __half, wmma::row_major> af[2];
            wmma::fragment<wmma::matrix_b, 16, 16, 16, __half, wmma::row_major> bf[4];
#pragma unroll
            for (int i = 0; i < 2; i++)
                wmma::load_matrix_sync(af[i], &As[s * ASTG + (wm * 32 + i * 16) * ALD + ks * 16], ALD);
#pragma unroll
            for (int j = 0; j < 4; j++)
                wmma::load_matrix_sync(bf[j], &Bs[s * BSTG + (ks * 16) * BLD + wn * 64 + j * 16], BLD);
#pragma unroll
            for (int i = 0; i < 2; i++)
#pragma unroll
                for (int j = 0; j < 4; j++)
                    wmma::mma_sync(acc[i][j], af[i], bf[j], acc[i][j]);
        }
        __syncthreads();
    }

    // Staged epilogue: fp32 acc -> fp16, coalesced 16B stores
    float* wbuf = (float*)smh + warp * 256;
    const int lr = lane >> 1;
    const int lc = (lane & 1) * 8;
#pragma unroll
    for (int i = 0; i < 2; i++) {
#pragma unroll
        for (int j = 0; j < 4; j++) {
            wmma::store_matrix_sync(wbuf, acc[i][j], 16, wmma::mem_row_major);
            __syncwarp();
            int m = m0 + wm * 32 + i * 16 + lr;
            int n = n0 + wn * 64 + j * 16 + lc;
            __half2 h[4];
#pragma unroll
            for (int e = 0; e < 4; e++)
                h[e] = __floats2half2_rn(wbuf[lr * 16 + lc + e * 2],
                                         wbuf[lr * 16 + lc + e * 2 + 1]);
            *(uint4*)&Ch[(size_t)m * ldc + n] = *(uint4*)h;
            __syncwarp();
        }
    }
}

// ---------------------------------------------------------------------------
// Chunk-parallel scan over fp16 bxby
// ---------------------------------------------------------------------------
__global__ void scanA_kernel(const __half* __restrict__ bxby,
                             float* __restrict__ e1, float* __restrict__ e2) {
    int idx = blockIdx.x * blockDim.x + threadIdx.x;    // B*C*H
    int h = idx & (H_ - 1);
    int j = (idx >> 10) & (C_ - 1);
    int b = idx >> 14;
    float gg = d_g[h], pp = d_phi[h];
    float c1 = 0.f, c2 = 0.f;
    const __half* base = bxby + ((size_t)(b * T_ + j * L_)) * (2 * H_) + h;
#pragma unroll 4
    for (int t = 0; t < L_; t++) {
        float bx = __half2float(base[t * (2 * H_)]);
        float by = __half2float(base[t * (2 * H_) + H_]);
        float n1 = fmaf(gg, c1, fmaf(-pp, c2, bx));
        float n2 = fmaf(pp, c1, fmaf(gg, c2, by));
        c1 = n1; c2 = n2;
    }
    e1[idx] = c1; e2[idx] = c2;
}

__global__ void combine_kernel(const float* __restrict__ e1,
                               const float* __restrict__ e2,
                               const float* __restrict__ hc1,
                               const float* __restrict__ hc2,
                               float* __restrict__ i1, float* __restrict__ i2) {
    int idx = blockIdx.x * blockDim.x + threadIdx.x;    // B*H
    int h = idx & (H_ - 1);
    int b = idx >> 10;
    float lr = d_g[h], li = d_phi[h];
#pragma unroll
    for (int s = 0; s < 7; s++) {          // lambda^128
        float nr = lr * lr - li * li;
        float ni = 2.0f * lr * li;
        lr = nr; li = ni;
    }
    float c1 = hc1[idx], c2 = hc2[idx];
#pragma unroll
    for (int j = 0; j < C_; j++) {
        int eidx = (b * C_ + j) * H_ + h;
        i1[eidx] = c1; i2[eidx] = c2;
        float n1 = lr * c1 - li * c2 + e1[eidx];
        float n2 = li * c1 + lr * c2 + e2[eidx];
        c1 = n1; c2 = n2;
    }
}

__global__ void scanB_kernel(const __half* __restrict__ bxby,
                             const float* __restrict__ i1,
                             const float* __restrict__ i2,
                             float* __restrict__ out) {
    int idx = blockIdx.x * blockDim.x + threadIdx.x;    // B*C*H
    int h = idx & (H_ - 1);
    int j = (idx >> 10) & (C_ - 1);
    int b = idx >> 14;
    float gg = d_g[h], pp = d_phi[h];
    float c1 = i1[idx], c2 = i2[idx];
    const __half* base = bxby + ((size_t)(b * T_ + j * L_)) * (2 * H_) + h;
    float*       ybase = out + ((size_t)(b * T_ + j * L_)) * (2 * H_) + h;
#pragma unroll 4
    for (int t = 0; t < L_; t++) {
        float bx = __half2float(base[t * (2 * H_)]);
        float by = __half2float(base[t * (2 * H_) + H_]);
        float n1 = fmaf(gg, c1, fmaf(-pp, c2, bx));
        float n2 = fmaf(pp, c1, fmaf(gg, c2, by));
        c1 = n1; c2 = n2;
        ybase[t * (2 * H_)]      = c1;
        ybase[t * (2 * H_) + H_] = c2;
    }
    if (j == C_ - 1) {
        size_t y_elems = (size_t)B_ * T_ * (2 * H_);
        out[y_elems + b * H_ + h]            = c1;
        out[y_elems + B_ * H_ + b * H_ + h]  = c2;
    }
}

// ---------------------------------------------------------------------------
// Launch
// ---------------------------------------------------------------------------
extern "C" void kernel_launch(void* const* d_in, const int* in_sizes, int n_in,
                              void* d_out, int out_size) {
    const float* x         = (const float*)d_in[0];
    const float* nu_log    = (const float*)d_in[1];
    const float* theta_log = (const float*)d_in[2];
    const float* U1        = (const float*)d_in[3];
    const float* U2        = (const float*)d_in[4];
    const float* V1        = (const float*)d_in[5];
    const float* V2        = (const float*)d_in[6];
    const float* hc1       = (const float*)d_in[7];
    const float* hc2       = (const float*)d_in[8];
    float* out = (float*)d_out;

    __half *xh, *u1h, *u2h, *v1h, *v2h, *tmph, *bxbyh;
    float *e1, *e2, *i1, *i2;
    cudaGetSymbolAddress((void**)&xh,    d_xh);
    cudaGetSymbolAddress((void**)&u1h,   d_u1h);
    cudaGetSymbolAddress((void**)&u2h,   d_u2h);
    cudaGetSymbolAddress((void**)&v1h,   d_v1h);
    cudaGetSymbolAddress((void**)&v2h,   d_v2h);
    cudaGetSymbolAddress((void**)&tmph,  d_tmph);
    cudaGetSymbolAddress((void**)&bxbyh, d_bxbyh);
    cudaGetSymbolAddress((void**)&e1, d_e1);
    cudaGetSymbolAddress((void**)&e2, d_e2);
    cudaGetSymbolAddress((void**)&i1, d_i1);
    cudaGetSymbolAddress((void**)&i2, d_i2);

    const int smem = 3 * (128 * 40 + 32 * 136) * 2;    // 56832 B
    cudaFuncSetAttribute(h16_gemm<0>, cudaFuncAttributeMaxDynamicSharedMemorySize, smem);
    cudaFuncSetAttribute(h16_gemm<1>, cudaFuncAttributeMaxDynamicSharedMemorySize, smem);

    // Prep: params + U/V conversion (gamma folded into V)
    prep_kernel<<<(R_ * H_ + 255) / 256, 256>>>(nu_log, theta_log, U1, U2, V1, V2);

    int n8 = (M_ * D_) / 8;
    conv_x_kernel<<<(n8 + 255) / 256, 256>>>(x, xh, n8);

    // Stage 1: tmph[:,0:128]=x@U1, tmph[:,128:256]=x@U2  (K=1024)
    h16_gemm<0><<<dim3(2, M_ / 128), 256, smem>>>(
        xh, D_, u1h, u2h, R_, R_, D_, tmph, 2 * R_);

    // Stage 2: bxby[:,0:H]=tmp1@(V1*g), bxby[:,H:2H]=tmp2@(V2*g)  (K=128, fp16)
    h16_gemm<1><<<dim3(2 * H_ / 128, M_ / 128), 256, smem>>>(
        tmph, 2 * R_, v1h, v2h, H_, H_, R_, bxbyh, 2 * H_);

    // Stage 3: chunk-parallel scan
    scanA_kernel<<<(B_ * C_ * H_) / 256, 256>>>(bxbyh, e1, e2);
    combine_kernel<<<(B_ * H_) / 256, 256>>>(e1, e2, hc1, hc2, i1, i2);
    scanB_kernel<<<(B_ * C_ * H_) / 256, 256>>>(bxbyh, i1, i2, out);
}

// round 14
// speedup vs baseline: 3.0328x; 1.0647x over previous
#include <cuda_runtime.h>
#include <cuda_fp16.h>
#include <cstdint>
#include <mma.h>

using namespace nvcuda;

// Problem constants
#define B_  8
#define T_  2048
#define D_  1024
#define H_  1024
#define R_  128
#define M_  (B_*T_)      // 16384 rows
#define C_  16           // scan chunks
#define L_  128          // chunk length (T_/C_)

// ---------------------------------------------------------------------------
// Scratch (device globals: allocation APIs are forbidden)
// ---------------------------------------------------------------------------
__device__ __half d_u1h[D_ * R_], d_u2h[D_ * R_];
__device__ __half d_v1h[R_ * H_], d_v2h[R_ * H_];   // pre-scaled by gamma
__device__ __half d_tmph[(size_t)M_ * 2 * R_];      // 8 MB: x@U1 | x@U2 (fp16)
__device__ __half d_bxbyh[(size_t)M_ * 2 * H_];     // 64 MB (fp16)
__device__ float d_e1[B_ * C_ * H_], d_e2[B_ * C_ * H_];
__device__ float d_i1[B_ * C_ * H_], d_i2[B_ * C_ * H_];
__device__ float d_g[H_], d_phi[H_];

// ---------------------------------------------------------------------------
// Prep: decay params + U conv + V conv (gamma recomputed per V-thread).
// ---------------------------------------------------------------------------
__global__ void prep_kernel(const float* __restrict__ nu_log,
                            const float* __restrict__ theta_log,
                            const float* __restrict__ U1,
                            const float* __restrict__ U2,
                            const float* __restrict__ V1,
                            const float* __restrict__ V2) {
    int i = blockIdx.x * blockDim.x + threadIdx.x;
    if (i < H_) {
        float r = expf(-expf(nu_log[i]));
        float th = expf(theta_log[i]);
        d_g[i]   = r * cosf(th);
        d_phi[i] = r * sinf(th);
    }
    if (i < D_ * R_) {
        d_u1h[i] = __float2half_rn(U1[i]);
        d_u2h[i] = __float2half_rn(U2[i]);
    }
    if (i < R_ * H_) {
        int h = i % H_;
        float r = expf(-expf(nu_log[h]));
        float gm = sqrtf(fmaxf(1.0f - r * r, 0.0f));
        d_v1h[i] = __float2half_rn(V1[i] * gm);
        d_v2h[i] = __float2half_rn(V2[i] * gm);
    }
}

// cp.async helpers
__device__ __forceinline__ void cp_async16(void* dst, const void* src) {
    unsigned s = (unsigned)__cvta_generic_to_shared(dst);
    asm volatile("cp.async.ca.shared.global [%0], [%1], 16;" :: "r"(s), "l"(src));
}
__device__ __forceinline__ void cp_commit() { asm volatile("cp.async.commit_group;"); }
template <int N>
__device__ __forceinline__ void cp_wait() { asm volatile("cp.async.wait_group %0;" :: "n"(N)); }

// ---------------------------------------------------------------------------
// Stage 1 (fused x conversion): tmph[M,256] = fp16(x) @ [U1|U2]
// BM=128, BN=256 (x read ONCE), 512 threads = 16 warps (4m x 4n; 32x64/warp),
// KT=32, double-buffered: A prefetched fp32 -> converted -> STS; B cp.async.
// Dynamic smem: 2*(128*40 + 32*264)*2 = 54272 B.
// ---------------------------------------------------------------------------
__global__ __launch_bounds__(512, 1)
void gemm1_fused(const float* __restrict__ x,
                 const __half* __restrict__ u1h, const __half* __restrict__ u2h,
                 __half* __restrict__ tmph) {
    constexpr int ALD = 40;     // 32 + 8 halves
    constexpr int BLD = 264;    // 256 + 8 halves
    constexpr int ASTG = 128 * ALD;
    constexpr int BSTG = 32 * BLD;

    extern __shared__ __align__(16) __half smh[];
    __half* As = smh;                  // [2][128][40]
    __half* Bs = smh + 2 * ASTG;       // [2][32][264]

    const int tid  = threadIdx.x;
    const int warp = tid >> 5;
    const int lane = tid & 31;
    const int wm = warp >> 2;          // 0..3
    const int wn = warp & 3;           // 0..3
    const int m0 = blockIdx.x * 128;

    // A loader: 128 rows x 32 fp32, 8 floats/thread
    const int a_row = tid >> 2, a_col = (tid & 3) * 8;
    // B loader: 32 rows x 256 halves, 16 halves/thread (2 cp.async16)
    const int b_row = tid >> 4, b_col = (tid & 15) * 16;
    const __half* bsrc = (b_col < R_) ? &u1h[b_col] : &u2h[b_col - R_];

    float4 pa[2];
    auto prefA = [&](int k0) {
        const float* ap = &x[(size_t)(m0 + a_row) * D_ + k0 + a_col];
        pa[0] = *(const float4*)ap;
        pa[1] = *(const float4*)(ap + 4);
    };
    auto stageA = [&](int s) {
        __half2 h[4];
        h[0] = __floats2half2_rn(pa[0].x, pa[0].y);
        h[1] = __floats2half2_rn(pa[0].z, pa[0].w);
        h[2] = __floats2half2_rn(pa[1].x, pa[1].y);
        h[3] = __floats2half2_rn(pa[1].z, pa[1].w);
        *(uint4*)&As[s * ASTG + a_row * ALD + a_col] = *(uint4*)h;
    };
    auto cpB = [&](int s, int k0) {
        const __half* bp = bsrc + (size_t)(k0 + b_row) * R_;
        cp_async16(&Bs[s * BSTG + b_row * BLD + b_col],     bp);
        cp_async16(&Bs[s * BSTG + b_row * BLD + b_col + 8], bp + 8);
        cp_commit();
    };

    wmma::fragment<wmma::accumulator, 16, 16, 16, float> acc[2][4];
#pragma unroll
    for (int i = 0; i < 2; i++)
#pragma unroll
        for (int j = 0; j < 4; j++) wmma::fill_fragment(acc[i][j], 0.0f);

    const int nK = D_ / 32;     // 32
    prefA(0);
    cpB(0, 0);

    for (int kt = 0; kt < nK; kt++) {
        const int s = kt & 1;
        stageA(s);
        if (kt + 1 < nK) {
            prefA((kt + 1) * 32);
            cpB(1 - s, (kt + 1) * 32);
            cp_wait<1>();
        } else {
            cp_wait<0>();
        }
        __syncthreads();

#pragma unroll
        for (int ks = 0; ks < 2; ks++) {
            wmma::fragment<wmma::matrix_a, 16, 16, 16, __half, wmma::row_major> af[2];
            wmma::fragment<wmma::matrix_b, 16, 16, 16, __half, wmma::row_major> bf[4];
#pragma unroll
            for (int i = 0; i < 2; i++)
                wmma::load_matrix_sync(af[i], &As[s * ASTG + (wm * 32 + i * 16) * ALD + ks * 16], ALD);
#pragma unroll
            for (int j = 0; j < 4; j++)
                wmma::load_matrix_sync(bf[j], &Bs[s * BSTG + (ks * 16) * BLD + wn * 64 + j * 16], BLD);
#pragma unroll
            for (int i = 0; i < 2; i++)
#pragma unroll
                for (int j = 0; j < 4; j++)
                    wmma::mma_sync(acc[i][j], af[i], bf[j], acc[i][j]);
        }
        __syncthreads();
    }

    // Epilogue: fp32 acc -> fp16, staged through smem, 16B stores
    float* wbuf = (float*)smh + warp * 256;
    const int lr = lane >> 1;
    const int lc = (lane & 1) * 8;
#pragma unroll
    for (int i = 0; i < 2; i++) {
#pragma unroll
        for (int j = 0; j < 4; j++) {
            wmma::store_matrix_sync(wbuf, acc[i][j], 16, wmma::mem_row_major);
            __syncwarp();
            int m = m0 + wm * 32 + i * 16 + lr;
            int n = wn * 64 + j * 16 + lc;
            __half2 h[4];
#pragma unroll
            for (int e = 0; e < 4; e++)
                h[e] = __floats2half2_rn(wbuf[lr * 16 + lc + e * 2],
                                         wbuf[lr * 16 + lc + e * 2 + 1]);
            *(uint4*)&tmph[(size_t)m * 256 + n] = *(uint4*)h;
            __syncwarp();
        }
    }
}

// ---------------------------------------------------------------------------
// Stage 2: fp16 wmma GEMM (unchanged from R13): BM=128, BN=128, KT=32;
// 256 threads; 3-stage cp.async; 2 CTAs/SM; fp16 staged output.
// DUALA: block with n0 >= nsplit reads A cols shifted +R_ (tmp2 half).
// ---------------------------------------------------------------------------
__global__ __launch_bounds__(256, 2)
void h16_gemm2(const __half* __restrict__ A, int lda,
               const __half* __restrict__ B0, const __half* __restrict__ B1,
               int ldb, int nsplit, int K,
               __half* __restrict__ Ch, int ldc) {
    constexpr int ALD = 40;
    constexpr int BLD = 136;
    constexpr int ASTG = 128 * ALD;
    constexpr int BSTG = 32 * BLD;

    extern __shared__ __align__(16) __half smh[];
    __half* As = smh;                  // [3][128][40]
    __half* Bs = smh + 3 * ASTG;       // [3][32][136]

    const int tid  = threadIdx.x;
    const int warp = tid >> 5;
    const int lane = tid & 31;
    const int wm = warp >> 1;
    const int wn = warp & 1;
    const int m0 = blockIdx.y * 128;
    const int n0 = blockIdx.x * 128;

    const __half* Bp = (n0 < nsplit) ? B0 : B1;
    const int bn0    = (n0 < nsplit) ? n0 : n0 - nsplit;
    const int aoff   = (n0 >= nsplit) ? R_ : 0;

    auto load_stage = [&](int s, int k0) {
#pragma unroll
        for (int i = 0; i < 2; i++) {
            int q = tid + i * 256;
            int ar = q >> 2, ac = (q & 3) * 8;
            cp_async16(&As[s * ASTG + ar * ALD + ac],
                       &A[(size_t)(m0 + ar) * lda + aoff + k0 + ac]);
        }
#pragma unroll
        for (int i = 0; i < 2; i++) {
            int q = tid + i * 256;
            int br = q >> 4, bc = (q & 15) * 8;
            cp_async16(&Bs[s * BSTG + br * BLD + bc],
                       &Bp[(size_t)(k0 + br) * ldb + bn0 + bc]);
        }
        cp_commit();
    };

    wmma::fragment<wmma::accumulator, 16, 16, 16, float> acc[2][4];
#pragma unroll
    for (int i = 0; i < 2; i++)
#pragma unroll
        for (int j = 0; j < 4; j++) wmma::fill_fragment(acc[i][j], 0.0f);

    const int nK = K / 32;
    load_stage(0, 0);
    if (nK > 1) load_stage(1, 32);

    for (int kt = 0; kt < nK; kt++) {
        const int s = kt % 3;
        if (kt + 2 < nK) { load_stage((kt + 2) % 3, (kt + 2) * 32); cp_wait<2>(); }
        else if (kt + 1 < nK) { cp_wait<1>(); }
        else { cp_wait<0>(); }
        __syncthreads();

#pragma unroll
        for (int ks = 0; ks < 2; ks++) {
            wmma::fragment<wmma::matrix_a, 16, 16, 16, __half, wmma::row_major> af[2];
            wmma::fragment<wmma::matrix_b, 16, 16, 16, __half, wmma::row_major> bf[4];
#pragma unroll
            for (int i = 0; i < 2; i++)
                wmma::load_matrix_sync(af[i], &As[s * ASTG + (wm * 32 + i * 16) * ALD + ks * 16], ALD);
#pragma unroll
            for (int j = 0; j < 4; j++)
                wmma::load_matrix_sync(bf[j], &Bs[s * BSTG + (ks * 16) * BLD + wn * 64 + j * 16], BLD);
#pragma unroll
            for (int i = 0; i < 2; i++)
#pragma unroll
                for (int j = 0; j < 4; j++)
                    wmma::mma_sync(acc[i][j], af[i], bf[j], acc[i][j]);
        }
        __syncthreads();
    }

    float* wbuf = (float*)smh + warp * 256;
    const int lr = lane >> 1;
    const int lc = (lane & 1) * 8;
#pragma unroll
    for (int i = 0; i < 2; i++) {
#pragma unroll
        for (int j = 0; j < 4; j++) {
            wmma::store_matrix_sync(wbuf, acc[i][j], 16, wmma::mem_row_major);
            __syncwarp();
            int m = m0 + wm * 32 + i * 16 + lr;
            int n = n0 + wn * 64 + j * 16 + lc;
            __half2 h[4];
#pragma unroll
            for (int e = 0; e < 4; e++)
                h[e] = __floats2half2_rn(wbuf[lr * 16 + lc + e * 2],
                                         wbuf[lr * 16 + lc + e * 2 + 1]);
            *(uint4*)&Ch[(size_t)m * ldc + n] = *(uint4*)h;
            __syncwarp();
        }
    }
}

// ---------------------------------------------------------------------------
// Chunk-parallel scan over fp16 bxby (unchanged)
// ---------------------------------------------------------------------------
__global__ void scanA_kernel(const __half* __restrict__ bxby,
                             float* __restrict__ e1, float* __restrict__ e2) {
    int idx = blockIdx.x * blockDim.x + threadIdx.x;
    int h = idx & (H_ - 1);
    int j = (idx >> 10) & (C_ - 1);
    int b = idx >> 14;
    float gg = d_g[h], pp = d_phi[h];
    float c1 = 0.f, c2 = 0.f;
    const __half* base = bxby + ((size_t)(b * T_ + j * L_)) * (2 * H_) + h;
#pragma unroll 4
    for (int t = 0; t < L_; t++) {
        float bx = __half2float(base[t * (2 * H_)]);
        float by = __half2float(base[t * (2 * H_) + H_]);
        float n1 = fmaf(gg, c1, fmaf(-pp, c2, bx));
        float n2 = fmaf(pp, c1, fmaf(gg, c2, by));
        c1 = n1; c2 = n2;
    }
    e1[idx] = c1; e2[idx] = c2;
}

__global__ void combine_kernel(const float* __restrict__ e1,
                               const float* __restrict__ e2,
                               const float* __restrict__ hc1,
                               const float* __restrict__ hc2,
                               float* __restrict__ i1, float* __restrict__ i2) {
    int idx = blockIdx.x * blockDim.x + threadIdx.x;
    int h = idx & (H_ - 1);
    int b = idx >> 10;
    float lr = d_g[h], li = d_phi[h];
#pragma unroll
    for (int s = 0; s < 7; s++) {
        float nr = lr * lr - li * li;
        float ni = 2.0f * lr * li;
        lr = nr; li = ni;
    }
    float c1 = hc1[idx], c2 = hc2[idx];
#pragma unroll
    for (int j = 0; j < C_; j++) {
        int eidx = (b * C_ + j) * H_ + h;
        i1[eidx] = c1; i2[eidx] = c2;
        float n1 = lr * c1 - li * c2 + e1[eidx];
        float n2 = li * c1 + lr * c2 + e2[eidx];
        c1 = n1; c2 = n2;
    }
}

__global__ void scanB_kernel(const __half* __restrict__ bxby,
                             const float* __restrict__ i1,
                             const float* __restrict__ i2,
                             float* __restrict__ out) {
    int idx = blockIdx.x * blockDim.x + threadIdx.x;
    int h = idx & (H_ - 1);
    int j = (idx >> 10) & (C_ - 1);
    int b = idx >> 14;
    float gg = d_g[h], pp = d_phi[h];
    float c1 = i1[idx], c2 = i2[idx];
    const __half* base = bxby + ((size_t)(b * T_ + j * L_)) * (2 * H_) + h;
    float*       ybase = out + ((size_t)(b * T_ + j * L_)) * (2 * H_) + h;
#pragma unroll 4
    for (int t = 0; t < L_; t++) {
        float bx = __half2float(base[t * (2 * H_)]);
        float by = __half2float(base[t * (2 * H_) + H_]);
        float n1 = fmaf(gg, c1, fmaf(-pp, c2, bx));
        float n2 = fmaf(pp, c1, fmaf(gg, c2, by));
        c1 = n1; c2 = n2;
        ybase[t * (2 * H_)]      = c1;
        ybase[t * (2 * H_) + H_] = c2;
    }
    if (j == C_ - 1) {
        size_t y_elems = (size_t)B_ * T_ * (2 * H_);
        out[y_elems + b * H_ + h]            = c1;
        out[y_elems + B_ * H_ + b * H_ + h]  = c2;
    }
}

// ---------------------------------------------------------------------------
// Launch
// ---------------------------------------------------------------------------
extern "C" void kernel_launch(void* const* d_in, const int* in_sizes, int n_in,
                              void* d_out, int out_size) {
    const float* x         = (const float*)d_in[0];
    const float* nu_log    = (const float*)d_in[1];
    const float* theta_log = (const float*)d_in[2];
    const float* U1        = (const float*)d_in[3];
    const float* U2        = (const float*)d_in[4];
    const float* V1        = (const float*)d_in[5];
    const float* V2        = (const float*)d_in[6];
    const float* hc1       = (const float*)d_in[7];
    const float* hc2       = (const float*)d_in[8];
    float* out = (float*)d_out;

    __half *u1h, *u2h, *v1h, *v2h, *tmph, *bxbyh;
    float *e1, *e2, *i1, *i2;
    cudaGetSymbolAddress((void**)&u1h,   d_u1h);
    cudaGetSymbolAddress((void**)&u2h,   d_u2h);
    cudaGetSymbolAddress((void**)&v1h,   d_v1h);
    cudaGetSymbolAddress((void**)&v2h,   d_v2h);
    cudaGetSymbolAddress((void**)&tmph,  d_tmph);
    cudaGetSymbolAddress((void**)&bxbyh, d_bxbyh);
    cudaGetSymbolAddress((void**)&e1, d_e1);
    cudaGetSymbolAddress((void**)&e2, d_e2);
    cudaGetSymbolAddress((void**)&i1, d_i1);
    cudaGetSymbolAddress((void**)&i2, d_i2);

    const int smem1 = 2 * (128 * 40 + 32 * 264) * 2;   // 54272 B
    const int smem2 = 3 * (128 * 40 + 32 * 136) * 2;   // 56832 B
    cudaFuncSetAttribute(gemm1_fused, cudaFuncAttributeMaxDynamicSharedMemorySize, smem1);
    cudaFuncSetAttribute(h16_gemm2, cudaFuncAttributeMaxDynamicSharedMemorySize, smem2);

    // Prep: params + U/V conversion (gamma folded into V)
    prep_kernel<<<(R_ * H_ + 255) / 256, 256>>>(nu_log, theta_log, U1, U2, V1, V2);

    // Stage 1 (fused x conversion): tmph = fp16(x) @ [U1|U2], x read once
    gemm1_fused<<<M_ / 128, 512, smem1>>>(x, u1h, u2h, tmph);

    // Stage 2: bxby[:,0:H]=tmp1@(V1*g), bxby[:,H:2H]=tmp2@(V2*g)  (K=128)
    h16_gemm2<<<dim3(2 * H_ / 128, M_ / 128), 256, smem2>>>(
        tmph, 2 * R_, v1h, v2h, H_, H_, R_, bxbyh, 2 * H_);

    // Stage 3: chunk-parallel scan
    scanA_kernel<<<(B_ * C_ * H_) / 256, 256>>>(bxbyh, e1, e2);
    combine_kernel<<<(B_ * H_) / 256, 256>>>(e1, e2, hc1, hc2, i1, i2);
    scanB_kernel<<<(B_ * C_ * H_) / 256, 256>>>(bxbyh, i1, i2, out);
}